// round 3
// baseline (speedup 1.0000x reference)
#include <cuda_runtime.h>
#include <math.h>

#define B_   4
#define S_   512
#define K_   32
#define V_   32000
#define ROWS (B_*S_)
#define NT   256
#define NW   (NT/32)
#define NF4  (V_/4)

// Merge two descending-sorted 8-lists (t, b), keep top-8 descending in t.
__device__ __forceinline__ void bitonic_top8_merge(float* t, const float* b) {
    float m[8];
    #pragma unroll
    for (int j = 0; j < 8; ++j) m[j] = fmaxf(t[j], b[7 - j]);
    #pragma unroll
    for (int j = 0; j < 4; ++j) {
        float hi = fmaxf(m[j], m[j + 4]), lo = fminf(m[j], m[j + 4]);
        m[j] = hi; m[j + 4] = lo;
    }
    #pragma unroll
    for (int jb = 0; jb < 8; jb += 4)
        #pragma unroll
        for (int j = 0; j < 2; ++j) {
            float hi = fmaxf(m[jb + j], m[jb + j + 2]), lo = fminf(m[jb + j], m[jb + j + 2]);
            m[jb + j] = hi; m[jb + j + 2] = lo;
        }
    #pragma unroll
    for (int j = 0; j < 8; j += 2) {
        float hi = fmaxf(m[j], m[j + 1]), lo = fminf(m[j], m[j + 1]);
        m[j] = hi; m[j + 1] = lo;
    }
    #pragma unroll
    for (int j = 0; j < 8; ++j) t[j] = m[j];
}

// Insert a single value into descending top-8 (rare path).
__device__ __forceinline__ void insert1(float x, float* t) {
    if (x > t[7]) {
        t[7] = x;
        #pragma unroll
        for (int j = 7; j > 0; --j)
            if (t[j] > t[j - 1]) { float tm = t[j - 1]; t[j - 1] = t[j]; t[j] = tm; }
    }
}

__global__ void __launch_bounds__(NT)
combiner_kernel(const int*   __restrict__ tgt,
                const float* __restrict__ dists,
                const float* __restrict__ keyf,
                const float* __restrict__ nprob,
                const float* __restrict__ selp,
                const float* __restrict__ Wf,  const float* __restrict__ bf,
                const float* __restrict__ W1a, const float* __restrict__ b1a,
                const float* __restrict__ W1b, const float* __restrict__ b1b,
                const float* __restrict__ W2a, const float* __restrict__ b2a,
                const float* __restrict__ W2b, const float* __restrict__ b2b,
                float* __restrict__ out, float* __restrict__ lam_out)
{
    const int row  = blockIdx.x;
    const int tid  = threadIdx.x;
    const int lane = tid & 31;
    const int warp = tid >> 5;
    const unsigned FULL = 0xffffffffu;

    __shared__ float s_d[K_], s_lk[K_], s_ls[K_], s_cnt[K_], s_probs[K_];
    __shared__ int   s_idx[K_];
    __shared__ float s_warp[NW][8];
    __shared__ float s_top8[8];
    __shared__ float s_lam;

    // ---- Phase 1 (warp 0): per-row small inputs + distinct-label prefix counts
    if (warp == 0) {
        const int base = row * K_;
        int v = tgt[base + lane];
        s_idx[lane] = v;
        s_d[lane]  = dists[base + lane];
        s_lk[lane] = logf(keyf[base + lane]);
        s_ls[lane] = logf(selp[base + lane]);
        bool dup = false;
        #pragma unroll
        for (int j = 0; j < 31; ++j) {
            int vj = __shfl_sync(FULL, v, j);
            if (j < lane && vj == v) dup = true;
        }
        unsigned m = __ballot_sync(FULL, (v != 0) && !dup);
        s_cnt[lane] = (float)__popc(m & ((2u << lane) - 1u));
    }

    // ---- Phase 2: read-only streaming top-8 scan (zeroing done by memset node)
    float t[8];
    #pragma unroll
    for (int j = 0; j < 8; ++j) t[j] = -1.0f;

    const float4* src = reinterpret_cast<const float4*>(nprob + (size_t)row * V_);

    int i = tid;
    #pragma unroll 1
    for (int ii = 0; ii < 7; ++ii, i += 4 * NT) {
        float4 a = __ldcs(src + i);
        float4 b = __ldcs(src + i + NT);
        float4 c = __ldcs(src + i + 2 * NT);
        float4 d = __ldcs(src + i + 3 * NT);
        // 15-op max tree over 16 values, ONE compare against running 8th-best
        float m01 = fmaxf(fmaxf(a.x, a.y), fmaxf(a.z, a.w));
        float m02 = fmaxf(fmaxf(b.x, b.y), fmaxf(b.z, b.w));
        float m03 = fmaxf(fmaxf(c.x, c.y), fmaxf(c.z, c.w));
        float m04 = fmaxf(fmaxf(d.x, d.y), fmaxf(d.z, d.w));
        float m16 = fmaxf(fmaxf(m01, m02), fmaxf(m03, m04));
        if (m16 > t[7]) {   // rare: ~8*ln(250) ≈ 44 triggers over whole scan per thread-group
            insert1(a.x, t); insert1(a.y, t); insert1(a.z, t); insert1(a.w, t);
            insert1(b.x, t); insert1(b.y, t); insert1(b.z, t); insert1(b.w, t);
            insert1(c.x, t); insert1(c.y, t); insert1(c.z, t); insert1(c.w, t);
            insert1(d.x, t); insert1(d.y, t); insert1(d.z, t); insert1(d.w, t);
        }
    }
    #pragma unroll 1
    for (; i < NF4; i += NT) {
        float4 a = __ldcs(src + i);
        float m4 = fmaxf(fmaxf(a.x, a.y), fmaxf(a.z, a.w));
        if (m4 > t[7]) { insert1(a.x, t); insert1(a.y, t); insert1(a.z, t); insert1(a.w, t); }
    }

    // ---- Phase 3: register/shuffle top-8 reduction
    #pragma unroll
    for (int off = 16; off >= 1; off >>= 1) {
        float b[8];
        #pragma unroll
        for (int j = 0; j < 8; ++j) b[j] = __shfl_down_sync(FULL, t[j], off);
        bitonic_top8_merge(t, b);
    }
    if (lane == 0) {
        #pragma unroll
        for (int j = 0; j < 8; ++j) s_warp[warp][j] = t[j];
    }
    __syncthreads();

    if (warp == 0) {
        float w[8];
        #pragma unroll
        for (int j = 0; j < 8; ++j) w[j] = (lane < NW) ? s_warp[lane & (NW - 1)][j] : -1.0f;
        #pragma unroll
        for (int off = 4; off >= 1; off >>= 1) {
            float b[8];
            #pragma unroll
            for (int j = 0; j < 8; ++j) b[j] = __shfl_down_sync(FULL, w[j], off);
            bitonic_top8_merge(w, b);
        }
        if (lane == 0) {
            #pragma unroll
            for (int j = 0; j < 8; ++j) s_top8[j] = w[j];
        }
        __syncwarp();

        // ---- Phase 4 (warp 0): MLPs, softmax, lambda
        float lk = s_lk[lane], ls = s_ls[lane], d = s_d[lane];

        float nl = b1b[0];
        #pragma unroll
        for (int j = 0; j < 4; ++j) {
            float h = tanhf(fmaf(W1a[2 * j], lk, fmaf(W1a[2 * j + 1], ls, b1a[j])));
            nl = fmaf(W1b[j], h, nl);
        }

        float acc = b2a[lane];
        #pragma unroll
        for (int dd = 0; dd < 32; ++dd) acc = fmaf(W2a[lane * 64 + dd],      s_d[dd],   acc);
        #pragma unroll
        for (int dd = 0; dd < 32; ++dd) acc = fmaf(W2a[lane * 64 + 32 + dd], s_cnt[dd], acc);
        float h2 = tanhf(acc);
        float l0 = W2b[lane]      * h2;
        float l1 = W2b[32 + lane] * h2;

        float sp = fmaf(Wf[8 + lane], lk, Wf[40 + lane] * ls);
        if (lane < 8) sp = fmaf(Wf[lane], logf(s_top8[lane]), sp);

        #pragma unroll
        for (int o = 16; o >= 1; o >>= 1) {
            l0 += __shfl_xor_sync(FULL, l0, o);
            l1 += __shfl_xor_sync(FULL, l1, o);
            sp += __shfl_xor_sync(FULL, sp, o);
        }
        l0 += b2b[0]; l1 += b2b[1];
        float sim   = sp + bf[0];
        float tempe = 1.f / (1.f + expf(-l1));

        float z  = fmaf(-d, tempe, nl);
        float mx = z;
        #pragma unroll
        for (int o = 16; o >= 1; o >>= 1) mx = fmaxf(mx, __shfl_xor_sync(FULL, mx, o));
        float e  = expf(z - mx);
        float se = e;
        #pragma unroll
        for (int o = 16; o >= 1; o >>= 1) se += __shfl_xor_sync(FULL, se, o);
        s_probs[lane] = e / se;

        if (lane == 0) s_lam = 1.f / (1.f + expf(-(l0 - sim)));

        __syncwarp();

        // ---- Phase 5: ordered scatter (last-wins for duplicates) + lambda
        if (lane == 0) {
            float* orow = out + (size_t)row * V_;
            #pragma unroll
            for (int k = 0; k < K_; ++k) orow[s_idx[k]] = s_probs[k];
            lam_out[row] = s_lam;
        }
    }
}

extern "C" void kernel_launch(void* const* d_in, const int* in_sizes, int n_in,
                              void* d_out, int out_size) {
    const int*   tgt   = (const int*)  d_in[0];
    const float* dists = (const float*)d_in[1];
    const float* keyf  = (const float*)d_in[2];
    const float* nprob = (const float*)d_in[3];
    const float* selp  = (const float*)d_in[4];
    const float* Wf    = (const float*)d_in[5];
    const float* bf    = (const float*)d_in[6];
    const float* W1a   = (const float*)d_in[7];
    const float* b1a   = (const float*)d_in[8];
    const float* W1b   = (const float*)d_in[9];
    const float* b1b   = (const float*)d_in[10];
    const float* W2a   = (const float*)d_in[11];
    const float* b2a   = (const float*)d_in[12];
    const float* W2b   = (const float*)d_in[13];
    const float* b2b   = (const float*)d_in[14];

    float* out = (float*)d_out;
    float* lam = out + ((size_t)out_size - ROWS);

    // Zero the knn_prob region at pure-write bandwidth (graph memset node).
    cudaMemsetAsync(out, 0, (size_t)ROWS * V_ * sizeof(float));

    combiner_kernel<<<ROWS, NT>>>(tgt, dists, keyf, nprob, selp,
                                  Wf, bf, W1a, b1a, W1b, b1b,
                                  W2a, b2a, W2b, b2b, out, lam);
}

// round 5
// speedup vs baseline: 1.2679x; 1.2679x over previous
#include <cuda_runtime.h>
#include <math.h>

#define B_   4
#define S_   512
#define K_   32
#define V_   32000
#define ROWS (B_*S_)
#define NT   256
#define NW   (NT/32)
#define NF4  (V_/4)

#define CMP2(x, y) { float _hi = fmaxf((x),(y)), _lo = fminf((x),(y)); (x) = _hi; (y) = _lo; }

// Sort 4 values descending: optimal 5-comparator network.
__device__ __forceinline__ void sort4_desc(float* v) {
    CMP2(v[0], v[1]); CMP2(v[2], v[3]);
    CMP2(v[0], v[2]); CMP2(v[1], v[3]);
    CMP2(v[1], v[2]);
}

// Merge two descending sorted-4 lists into descending sorted-8 (bitonic, 12 comparators).
__device__ __forceinline__ void merge44_desc(const float* p, const float* q, float* x) {
    x[0] = p[0]; x[1] = p[1]; x[2] = p[2]; x[3] = p[3];
    x[4] = q[3]; x[5] = q[2]; x[6] = q[1]; x[7] = q[0];   // desc ++ asc = bitonic
    CMP2(x[0], x[4]); CMP2(x[1], x[5]); CMP2(x[2], x[6]); CMP2(x[3], x[7]);
    CMP2(x[0], x[2]); CMP2(x[1], x[3]); CMP2(x[4], x[6]); CMP2(x[5], x[7]);
    CMP2(x[0], x[1]); CMP2(x[2], x[3]); CMP2(x[4], x[5]); CMP2(x[6], x[7]);
}

// Merge two descending-sorted 8-lists, keep top-8 descending in t (8 max + 12 comparators).
__device__ __forceinline__ void bitonic_top8_merge(float* t, const float* b) {
    float m[8];
    #pragma unroll
    for (int j = 0; j < 8; ++j) m[j] = fmaxf(t[j], b[7 - j]);   // bitonic top-half
    CMP2(m[0], m[4]); CMP2(m[1], m[5]); CMP2(m[2], m[6]); CMP2(m[3], m[7]);
    CMP2(m[0], m[2]); CMP2(m[1], m[3]); CMP2(m[4], m[6]); CMP2(m[5], m[7]);
    CMP2(m[0], m[1]); CMP2(m[2], m[3]); CMP2(m[4], m[5]); CMP2(m[6], m[7]);
    #pragma unroll
    for (int j = 0; j < 8; ++j) t[j] = m[j];
}

// Branch-free: fold 16 values into running descending top-8 t.
__device__ __forceinline__ void fold16(float4 a, float4 b, float4 c, float4 d, float* t) {
    float va[4] = {a.x, a.y, a.z, a.w};
    float vb[4] = {b.x, b.y, b.z, b.w};
    float vc[4] = {c.x, c.y, c.z, c.w};
    float vd[4] = {d.x, d.y, d.z, d.w};
    sort4_desc(va); sort4_desc(vb); sort4_desc(vc); sort4_desc(vd);
    float s1[8], s2[8];
    merge44_desc(va, vb, s1);
    merge44_desc(vc, vd, s2);
    bitonic_top8_merge(t, s1);
    bitonic_top8_merge(t, s2);
}

// Tail-only rare insert.
__device__ __forceinline__ void insert1(float x, float* t) {
    if (x > t[7]) {
        t[7] = x;
        #pragma unroll
        for (int j = 7; j > 0; --j)
            if (t[j] > t[j - 1]) { float tm = t[j - 1]; t[j - 1] = t[j]; t[j] = tm; }
    }
}

__global__ void __launch_bounds__(NT)
combiner_kernel(const int*   __restrict__ tgt,
                const float* __restrict__ dists,
                const float* __restrict__ keyf,
                const float* __restrict__ nprob,
                const float* __restrict__ selp,
                const float* __restrict__ Wf,  const float* __restrict__ bf,
                const float* __restrict__ W1a, const float* __restrict__ b1a,
                const float* __restrict__ W1b, const float* __restrict__ b1b,
                const float* __restrict__ W2a, const float* __restrict__ b2a,
                const float* __restrict__ W2b, const float* __restrict__ b2b,
                float* __restrict__ out, float* __restrict__ lam_out)
{
    const int row  = blockIdx.x;
    const int tid  = threadIdx.x;
    const int lane = tid & 31;
    const int warp = tid >> 5;
    const unsigned FULL = 0xffffffffu;

    __shared__ float s_d[K_], s_lk[K_], s_ls[K_], s_cnt[K_], s_probs[K_];
    __shared__ int   s_idx[K_];
    __shared__ float s_warp[NW][8];
    __shared__ float s_top8[8];
    __shared__ float s_lam;

    // ---- Phase 1 (warp 0): per-row small inputs + distinct-label prefix counts
    if (warp == 0) {
        const int base = row * K_;
        int v = tgt[base + lane];
        s_idx[lane] = v;
        s_d[lane]  = dists[base + lane];
        s_lk[lane] = logf(keyf[base + lane]);
        s_ls[lane] = logf(selp[base + lane]);
        bool dup = false;
        #pragma unroll
        for (int j = 0; j < 31; ++j) {
            int vj = __shfl_sync(FULL, v, j);
            if (j < lane && vj == v) dup = true;
        }
        unsigned m = __ballot_sync(FULL, (v != 0) && !dup);
        s_cnt[lane] = (float)__popc(m & ((2u << lane) - 1u));
    }

    // ---- Phase 2: fused streaming scan (branch-free top-8) + zero-store
    float t[8];
    #pragma unroll
    for (int j = 0; j < 8; ++j) t[j] = -1.0f;

    const float4* src = reinterpret_cast<const float4*>(nprob + (size_t)row * V_);
    float4*       dst = reinterpret_cast<float4*>(out  + (size_t)row * V_);
    const float4  z4  = make_float4(0.f, 0.f, 0.f, 0.f);

    int i = tid;
    #pragma unroll 1
    for (int ii = 0; ii < 7; ++ii, i += 4 * NT) {
        float4 a = __ldcs(src + i);
        float4 b = __ldcs(src + i + NT);
        float4 c = __ldcs(src + i + 2 * NT);
        float4 d = __ldcs(src + i + 3 * NT);
        __stcs(dst + i,          z4);
        __stcs(dst + i + NT,     z4);
        __stcs(dst + i + 2 * NT, z4);
        __stcs(dst + i + 3 * NT, z4);
        fold16(a, b, c, d, t);
    }
    #pragma unroll 1
    for (; i < NF4; i += NT) {   // small tail: 3 strided iters + partial
        float4 a = __ldcs(src + i);
        __stcs(dst + i, z4);
        float m4 = fmaxf(fmaxf(a.x, a.y), fmaxf(a.z, a.w));
        if (m4 > t[7]) { insert1(a.x, t); insert1(a.y, t); insert1(a.z, t); insert1(a.w, t); }
    }

    // ---- Phase 3: register/shuffle top-8 reduction
    #pragma unroll
    for (int off = 16; off >= 1; off >>= 1) {
        float b[8];
        #pragma unroll
        for (int j = 0; j < 8; ++j) b[j] = __shfl_down_sync(FULL, t[j], off);
        bitonic_top8_merge(t, b);
    }
    if (lane == 0) {
        #pragma unroll
        for (int j = 0; j < 8; ++j) s_warp[warp][j] = t[j];
    }
    __syncthreads();   // orders phase-1 smem, warp results, and global zero-stores

    if (warp == 0) {
        float w[8];
        #pragma unroll
        for (int j = 0; j < 8; ++j) w[j] = (lane < NW) ? s_warp[lane & (NW - 1)][j] : -1.0f;
        #pragma unroll
        for (int off = 4; off >= 1; off >>= 1) {
            float b[8];
            #pragma unroll
            for (int j = 0; j < 8; ++j) b[j] = __shfl_down_sync(FULL, w[j], off);
            bitonic_top8_merge(w, b);
        }
        if (lane == 0) {
            #pragma unroll
            for (int j = 0; j < 8; ++j) s_top8[j] = w[j];
        }
        __syncwarp();

        // ---- Phase 4 (warp 0): MLPs, softmax, lambda
        float lk = s_lk[lane], ls = s_ls[lane], d = s_d[lane];

        float nl = b1b[0];
        #pragma unroll
        for (int j = 0; j < 4; ++j) {
            float h = tanhf(fmaf(W1a[2 * j], lk, fmaf(W1a[2 * j + 1], ls, b1a[j])));
            nl = fmaf(W1b[j], h, nl);
        }

        float acc = b2a[lane];
        #pragma unroll
        for (int dd = 0; dd < 32; ++dd) acc = fmaf(W2a[lane * 64 + dd],      s_d[dd],   acc);
        #pragma unroll
        for (int dd = 0; dd < 32; ++dd) acc = fmaf(W2a[lane * 64 + 32 + dd], s_cnt[dd], acc);
        float h2 = tanhf(acc);
        float l0 = W2b[lane]      * h2;
        float l1 = W2b[32 + lane] * h2;

        float sp = fmaf(Wf[8 + lane], lk, Wf[40 + lane] * ls);
        if (lane < 8) sp = fmaf(Wf[lane], logf(s_top8[lane]), sp);

        #pragma unroll
        for (int o = 16; o >= 1; o >>= 1) {
            l0 += __shfl_xor_sync(FULL, l0, o);
            l1 += __shfl_xor_sync(FULL, l1, o);
            sp += __shfl_xor_sync(FULL, sp, o);
        }
        l0 += b2b[0]; l1 += b2b[1];
        float sim   = sp + bf[0];
        float tempe = 1.f / (1.f + expf(-l1));

        float z  = fmaf(-d, tempe, nl);
        float mx = z;
        #pragma unroll
        for (int o = 16; o >= 1; o >>= 1) mx = fmaxf(mx, __shfl_xor_sync(FULL, mx, o));
        float e  = expf(z - mx);
        float se = e;
        #pragma unroll
        for (int o = 16; o >= 1; o >>= 1) se += __shfl_xor_sync(FULL, se, o);
        s_probs[lane] = e / se;

        if (lane == 0) s_lam = 1.f / (1.f + expf(-(l0 - sim)));
    }
    __syncthreads();

    // ---- Phase 5: ordered scatter (last-wins for duplicates) + lambda
    if (tid == 0) {
        float* orow = out + (size_t)row * V_;
        #pragma unroll
        for (int k = 0; k < K_; ++k) orow[s_idx[k]] = s_probs[k];
        lam_out[row] = s_lam;
    }
}

extern "C" void kernel_launch(void* const* d_in, const int* in_sizes, int n_in,
                              void* d_out, int out_size) {
    const int*   tgt   = (const int*)  d_in[0];
    const float* dists = (const float*)d_in[1];
    const float* keyf  = (const float*)d_in[2];
    const float* nprob = (const float*)d_in[3];
    const float* selp  = (const float*)d_in[4];
    const float* Wf    = (const float*)d_in[5];
    const float* bf    = (const float*)d_in[6];
    const float* W1a   = (const float*)d_in[7];
    const float* b1a   = (const float*)d_in[8];
    const float* W1b   = (const float*)d_in[9];
    const float* b1b   = (const float*)d_in[10];
    const float* W2a   = (const float*)d_in[11];
    const float* b2a   = (const float*)d_in[12];
    const float* W2b   = (const float*)d_in[13];
    const float* b2b   = (const float*)d_in[14];

    float* out = (float*)d_out;
    float* lam = out + ((size_t)out_size - ROWS);

    combiner_kernel<<<ROWS, NT>>>(tgt, dists, keyf, nprob, selp,
                                  Wf, bf, W1a, b1a, W1b, b1b,
                                  W2a, b2a, W2b, b2b, out, lam);
}